// round 10
// baseline (speedup 1.0000x reference)
#include <cuda_runtime.h>
#include <cuda_bf16.h>
#include <cstdint>

// Problem constants (fixed by the reference: LENGTHS[i] = 1024 + 128*i, B=16)
#define T_TOK   31744
#define PREV    768
#define DIM     256
#define NDOCS   16
#define MAXLEN  2944

// GEMM tiling: CTA 64x256, 8 warps as 2(M) x 4(N), warp tile 32x64
#define BM 64
#define BN 256
#define BK 32
#define NTHREADS 256
#define KTILES (PREV / BK)             // 24

// Fragment-major smem stages (u32 elements): 2-stage A, 3-stage B
#define A_STAGE (BM * BK)              // 2048 u32 = 8 KB
#define B_STAGE (BK * BN)              // 8192 u32 = 32 KB
#define SMEM_BYTES ((2 * A_STAGE + 3 * B_STAGE) * 4)   // 114688 B -> 2 CTAs/SM

#define GRID_GEMM (T_TOK / BM)         // 496
#define PAD_ROWS  (NDOCS * MAXLEN - T_TOK)  // 15360 = 480 * 32
#define ZCTAS     480
#define ZROWS     32                   // pad rows zeroed per CTA (bx < ZCTAS)

// W pre-rounded to tf32 bits, permuted to per-K-tile fragment-major order
__device__ uint32_t g_WT[PREV * DIM];

// ---------------- helpers ----------------
__device__ __forceinline__ int doc_offset(int b) { return 1024 * b + 64 * b * (b - 1); }
__device__ __forceinline__ int pad_offset(int b) { return 1920 * b - 64 * b * (b - 1); }

__device__ __forceinline__ int out_row_for_token(int t) {
    int b = 0;
#pragma unroll
    for (int i = 1; i < NDOCS; ++i) if (t >= doc_offset(i)) b = i;
    return b * MAXLEN + (t - doc_offset(b));
}
__device__ __forceinline__ int out_row_for_pad(int p) {
    int b = 0;
#pragma unroll
    for (int i = 1; i < NDOCS; ++i) if (p >= pad_offset(i)) b = i;
    return b * MAXLEN + (1024 + 128 * b) + (p - pad_offset(b));
}

__device__ __forceinline__ uint32_t f32_to_tf32(float f) {
    uint32_t r;
    asm("cvt.rna.tf32.f32 %0, %1;" : "=r"(r) : "f"(f));
    return r;
}
__device__ __forceinline__ uint32_t smem_u32_addr(const void* p) {
    uint32_t a;
    asm("{ .reg .u64 t; cvta.to.shared.u64 t, %1; cvt.u32.u64 %0, t; }" : "=r"(a) : "l"(p));
    return a;
}

__device__ __forceinline__ void mma_tf32(float* d, const uint32_t* a, const uint32_t* b) {
    asm volatile(
        "mma.sync.aligned.m16n8k8.row.col.f32.tf32.tf32.f32 "
        "{%0,%1,%2,%3}, {%4,%5,%6,%7}, {%8,%9}, {%0,%1,%2,%3};"
        : "+f"(d[0]), "+f"(d[1]), "+f"(d[2]), "+f"(d[3])
        : "r"(a[0]), "r"(a[1]), "r"(a[2]), "r"(a[3]), "r"(b[0]), "r"(b[1]));
}

#define CP_ASYNC16(dst_u32, src_ptr) \
    asm volatile("cp.async.cg.shared.global [%0], [%1], 16;" \
                 :: "r"(dst_u32), "l"(src_ptr) : "memory")
#define CP_COMMIT() asm volatile("cp.async.commit_group;" ::: "memory")
#define CP_WAIT0()  asm volatile("cp.async.wait_group 0;" ::: "memory")
#define CP_WAIT1()  asm volatile("cp.async.wait_group 1;" ::: "memory")

// B fragment-major address (u32 index) within one 32x256 K-tile
__host__ __device__ __forceinline__ int b_frag_addr(int n, int kl) {
    int warpN = n >> 6, ni = (n >> 3) & 7, gid = n & 7;
    int kk = kl >> 3, t4 = kl & 3, half = (kl >> 2) & 1;
    return ((((kk * 4 + warpN) * 8 + ni) * 8 + gid) * 4 + t4) * 2 + half;
}

// A fragment-major address with XOR swizzle (see R9)
__device__ __forceinline__ int a_frag_addr(int m, int kl) {
    int warpM = m >> 5, mi = (m >> 4) & 1, bit3 = (m >> 3) & 1, gid = m & 7;
    int kk = kl >> 3, t4 = kl & 3, half = (kl >> 2) & 1;
    int t4s = (t4 ^ (gid & 3) ^ kk) & 3;
    return ((((kk * 2 + warpM) * 2 + mi) * 8 + gid) * 4 + t4s) * 4 + half * 2 + bit3;
}

// ---------------- W round + permute kernel (tiny, one-time) ----------------
__global__ void round_w_kernel(const float* __restrict__ W) {
    int i = blockIdx.x * 256 + threadIdx.x;     // over PREV*DIM
    int k = i / DIM, n = i - k * DIM;
    int kt = k >> 5, kl = k & 31;
    g_WT[kt * B_STAGE + b_frag_addr(n, kl)] = f32_to_tf32(W[i]);
}

// ---------------- main fused kernel ----------------
__global__ __launch_bounds__(NTHREADS, 2)
void gemm_tc_scatter_kernel(const float* __restrict__ A,
                            const float* __restrict__ bias,
                            float* __restrict__ out) {
    extern __shared__ uint32_t sm[];
    uint32_t* AsBase = sm;                    // [2][A_STAGE] fragment-major
    uint32_t* BsBase = sm + 2 * A_STAGE;      // [3][B_STAGE] fragment-major

    const int tid = threadIdx.x;
    const int bx  = blockIdx.x;

    const int lane   = tid & 31;
    const int warpId = tid >> 5;
    const int warpM  = warpId & 1;      // 0..1 -> 32 rows each
    const int warpN  = warpId >> 1;     // 0..3 -> 64 cols each
    const int nb     = warpN * 64;
    const int gid    = lane >> 2;       // 0..7
    const int t4     = lane & 3;        // 0..3

    const int m0 = bx * BM;

    // A fill coords: thread loads rows am0, am0+32 at ks ak..ak+3 (float4)
    const int am0 = tid >> 3;                 // 0..31
    const int am1 = am0 + 32;
    const int ak  = (tid & 7) * 4;            // 0,4,...,28
    const float* aP0 = A + (size_t)(m0 + am0) * PREV + ak;
    const float* aP1 = A + (size_t)(m0 + am1) * PREV + ak;

    int sa0[4], sa1[4];
#pragma unroll
    for (int j = 0; j < 4; ++j) {
        sa0[j] = a_frag_addr(am0, ak + j);
        sa1[j] = a_frag_addr(am1, ak + j);
    }

    const uint32_t bsm = smem_u32_addr(BsBase);

    float acc[2][8][4];
#pragma unroll
    for (int mi = 0; mi < 2; ++mi)
#pragma unroll
        for (int ni = 0; ni < 8; ++ni)
#pragma unroll
            for (int j = 0; j < 4; ++j) acc[mi][ni][j] = 0.f;

    // ---- prologue: A0 sts(frag); B0, B1 cp.async (separate groups); A1 ldg ----
    {
        float4 a0 = *reinterpret_cast<const float4*>(aP0);
        float4 a1 = *reinterpret_cast<const float4*>(aP1);
        uint32_t* As = AsBase;
        As[sa0[0]] = f32_to_tf32(a0.x); As[sa0[1]] = f32_to_tf32(a0.y);
        As[sa0[2]] = f32_to_tf32(a0.z); As[sa0[3]] = f32_to_tf32(a0.w);
        As[sa1[0]] = f32_to_tf32(a1.x); As[sa1[1]] = f32_to_tf32(a1.y);
        As[sa1[2]] = f32_to_tf32(a1.z); As[sa1[3]] = f32_to_tf32(a1.w);
#pragma unroll
        for (int i = 0; i < 8; ++i) {
            int c = tid + i * NTHREADS;
            CP_ASYNC16(bsm + (uint32_t)c * 16, g_WT + c * 4);
        }
        CP_COMMIT();
#pragma unroll
        for (int i = 0; i < 8; ++i) {
            int c = tid + i * NTHREADS;
            CP_ASYNC16(bsm + (uint32_t)(B_STAGE + c * 4) * 4, g_WT + B_STAGE + c * 4);
        }
        CP_COMMIT();
    }
    float4 pa0 = *reinterpret_cast<const float4*>(aP0 + BK);
    float4 pa1 = *reinterpret_cast<const float4*>(aP1 + BK);

    int bs_cur = 0;      // B stage of tile kt
    int bs_pf  = 2;      // B stage for tile kt+2

    for (int kt = 0; kt < KTILES; ++kt) {
        const int acur = kt & 1;
        const int anxt = acur ^ 1;
        const bool more = (kt + 1 < KTILES);

        if (more) CP_WAIT1(); else CP_WAIT0();   // B(kt) resident, B(kt+1) may fly
        __syncthreads();                         // all reads of stage bs_pf done

        // commit B(kt+2) into stage bs_pf (has ~2 tiles of compute to land)
        if (kt + 2 < KTILES) {
            const uint32_t* src = g_WT + (size_t)(kt + 2) * B_STAGE;
#pragma unroll
            for (int i = 0; i < 8; ++i) {
                int c = tid + i * NTHREADS;
                CP_ASYNC16(bsm + (uint32_t)(bs_pf * B_STAGE + c * 4) * 4, src + c * 4);
            }
            CP_COMMIT();
        }

        // ---- compute current stage: 4 k-steps, fragment-native loads ----
        const uint32_t* As = AsBase + acur * A_STAGE;
        const uint32_t* Bs = BsBase + bs_cur * B_STAGE;
#pragma unroll
        for (int kk = 0; kk < 4; ++kk) {
            uint32_t af[2][4];
#pragma unroll
            for (int mi = 0; mi < 2; ++mi) {
                int g = ((((kk * 2 + warpM) * 2 + mi) * 8 + gid) * 4 +
                         ((t4 ^ (gid & 3) ^ kk) & 3)) * 4;
                uint4 v = *reinterpret_cast<const uint4*>(As + g);
                af[mi][0] = v.x; af[mi][1] = v.y; af[mi][2] = v.z; af[mi][3] = v.w;
            }
            uint32_t bf[8][2];
#pragma unroll
            for (int ni = 0; ni < 8; ++ni) {
                int g = ((((kk * 4 + warpN) * 8 + ni) * 8 + gid) * 4 + t4) * 2;
                uint2 v = *reinterpret_cast<const uint2*>(Bs + g);
                bf[ni][0] = v.x; bf[ni][1] = v.y;
            }
#pragma unroll
            for (int ni = 0; ni < 8; ++ni) {
                mma_tf32(acc[0][ni], af[0], bf[ni]);
                mma_tf32(acc[1][ni], af[1], bf[ni]);
            }
        }

        // ---- store A(kt+1) into anxt; prefetch A(kt+2) ----
        if (more) {
            uint32_t* Asn = AsBase + anxt * A_STAGE;
            Asn[sa0[0]] = f32_to_tf32(pa0.x); Asn[sa0[1]] = f32_to_tf32(pa0.y);
            Asn[sa0[2]] = f32_to_tf32(pa0.z); Asn[sa0[3]] = f32_to_tf32(pa0.w);
            Asn[sa1[0]] = f32_to_tf32(pa1.x); Asn[sa1[1]] = f32_to_tf32(pa1.y);
            Asn[sa1[2]] = f32_to_tf32(pa1.z); Asn[sa1[3]] = f32_to_tf32(pa1.w);
            if (kt + 2 < KTILES) {
                const int k0 = (kt + 2) * BK;
                pa0 = *reinterpret_cast<const float4*>(aP0 + k0);
                pa1 = *reinterpret_cast<const float4*>(aP1 + k0);
            }
        }

        if (++bs_cur == 3) bs_cur = 0;
        if (++bs_pf  == 3) bs_pf  = 0;
    }

    // ---- epilogue: bias + ragged scatter ----
    float2 bv[8];
#pragma unroll
    for (int ni = 0; ni < 8; ++ni)
        bv[ni] = *reinterpret_cast<const float2*>(bias + nb + ni * 8 + 2 * t4);

#pragma unroll
    for (int mi = 0; mi < 2; ++mi) {
        const int r0 = m0 + warpM * 32 + mi * 16 + gid;
        const int o0 = out_row_for_token(r0);
        const int o1 = out_row_for_token(r0 + 8);
        float* p0 = out + (size_t)o0 * DIM + nb + 2 * t4;
        float* p1 = out + (size_t)o1 * DIM + nb + 2 * t4;
#pragma unroll
        for (int ni = 0; ni < 8; ++ni) {
            float2 v0, v1;
            v0.x = acc[mi][ni][0] + bv[ni].x;
            v0.y = acc[mi][ni][1] + bv[ni].y;
            v1.x = acc[mi][ni][2] + bv[ni].x;
            v1.y = acc[mi][ni][3] + bv[ni].y;
            *reinterpret_cast<float2*>(p0 + ni * 8) = v0;
            *reinterpret_cast<float2*>(p1 + ni * 8) = v1;
        }
    }

    // ---- fused pad-zeroing: CTAs 0..479 each zero 32 padding rows ----
    if (bx < ZCTAS) {
        const int p0 = bx * ZROWS;
#pragma unroll 4
        for (int i = tid; i < ZROWS * (DIM / 4); i += NTHREADS) {
            int row = out_row_for_pad(p0 + (i >> 6));
            reinterpret_cast<float4*>(out + (size_t)row * DIM)[i & 63] =
                make_float4(0.f, 0.f, 0.f, 0.f);
        }
    }
}

extern "C" void kernel_launch(void* const* d_in, const int* in_sizes, int n_in,
                              void* d_out, int out_size) {
    const float* A    = (const float*)d_in[0];  // sent_embs [T_TOK, PREV]
    const float* W    = (const float*)d_in[1];  // [PREV, DIM]
    const float* bias = (const float*)d_in[2];  // [DIM]
    float* out = (float*)d_out;                 // [NDOCS*MAXLEN, DIM]

    cudaFuncSetAttribute(gemm_tc_scatter_kernel,
                         cudaFuncAttributeMaxDynamicSharedMemorySize, SMEM_BYTES);

    round_w_kernel<<<(PREV * DIM) / 256, 256>>>(W);
    gemm_tc_scatter_kernel<<<GRID_GEMM, NTHREADS, SMEM_BYTES>>>(A, bias, out);
}

// round 11
// speedup vs baseline: 1.5320x; 1.5320x over previous
#include <cuda_runtime.h>
#include <cuda_fp16.h>
#include <cstdint>

// Problem constants (fixed by the reference: LENGTHS[i] = 1024 + 128*i, B=16)
#define T_TOK   31744
#define PREV    768
#define DIM     256
#define NDOCS   16
#define MAXLEN  2944

// GEMM tiling: CTA 64x256, 8 warps as 2(M) x 4(N), warp tile 32x64, fp16 k16
#define BM 64
#define BN 256
#define BK 32
#define NTHREADS 256
#define KTILES (PREV / BK)             // 24

// Fragment-major smem stages (u32 elements), fp16 data
#define A_STAGE 1024                   // 64x32 fp16 = 4 KB
#define B_STAGE 4096                   // 32x256 fp16 = 16 KB
#define SMEM_BYTES ((2 * A_STAGE + 2 * B_STAGE) * 4)   // 40960 B

#define GRID_GEMM (T_TOK / BM)         // 496
#define PAD_ROWS  (NDOCS * MAXLEN - T_TOK)  // 15360
#define ZBLOCKS   120
#define ROWS_PER_Z (PAD_ROWS / ZBLOCKS)     // 128

// W pre-converted to fp16, permuted to per-K-tile fragment-major order.
// Per K-tile: 8192 halves; half index = u32_frag_index*2 + half.
__device__ uint16_t g_WH[PREV * DIM];

// ---------------- helpers ----------------
__device__ __forceinline__ int doc_offset(int b) { return 1024 * b + 64 * b * (b - 1); }
__device__ __forceinline__ int pad_offset(int b) { return 1920 * b - 64 * b * (b - 1); }

__device__ __forceinline__ int out_row_for_token(int t) {
    int b = 0;
#pragma unroll
    for (int i = 1; i < NDOCS; ++i) if (t >= doc_offset(i)) b = i;
    return b * MAXLEN + (t - doc_offset(b));
}
__device__ __forceinline__ int out_row_for_pad(int p) {
    int b = 0;
#pragma unroll
    for (int i = 1; i < NDOCS; ++i) if (p >= pad_offset(i)) b = i;
    return b * MAXLEN + (1024 + 128 * b) + (p - pad_offset(b));
}

__device__ __forceinline__ uint32_t smem_u32_addr(const void* p) {
    uint32_t a;
    asm("{ .reg .u64 t; cvta.to.shared.u64 t, %1; cvt.u32.u64 %0, t; }" : "=r"(a) : "l"(p));
    return a;
}

// fp16 MMA: D(4xf32) += A(4regs f16x2) * B(2regs f16x2)
__device__ __forceinline__ void mma_f16(float* d, const uint32_t* a, const uint32_t* b) {
    asm volatile(
        "mma.sync.aligned.m16n8k16.row.col.f32.f16.f16.f32 "
        "{%0,%1,%2,%3}, {%4,%5,%6,%7}, {%8,%9}, {%0,%1,%2,%3};"
        : "+f"(d[0]), "+f"(d[1]), "+f"(d[2]), "+f"(d[3])
        : "r"(a[0]), "r"(a[1]), "r"(a[2]), "r"(a[3]), "r"(b[0]), "r"(b[1]));
}

#define CP_ASYNC16(dst_u32, src_ptr) \
    asm volatile("cp.async.cg.shared.global [%0], [%1], 16;" \
                 :: "r"(dst_u32), "l"(src_ptr) : "memory")
#define CP_COMMIT() asm volatile("cp.async.commit_group;" ::: "memory")
#define CP_WAIT0()  asm volatile("cp.async.wait_group 0;" ::: "memory")

// B fragment-major HALF address within one 32x256 K-tile (8192 halves).
// m16n8k16 B frag: reg0 holds k={2t4,2t4+1}, reg1 holds k={2t4+8,2t4+9}, col=gid.
__host__ __device__ __forceinline__ int b_frag_half(int n, int kl) {
    int warpN = n >> 6, ni = (n >> 3) & 7, gid = n & 7;
    int kk = kl >> 4, k16 = kl & 15;
    int reg = k16 >> 3, t4 = (k16 & 7) >> 1, half = k16 & 1;
    int u32idx = ((((kk * 4 + warpN) * 8 + ni) * 8 + gid) * 4 + t4) * 2 + reg;
    return u32idx * 2 + half;
}

// A fragment-major U32 address within one 64x32 K-tile (1024 u32), XOR swizzle.
// m16n8k16 A frag regs: r = khi*2 + rowbit8 (a0:row gid klow, a1:row gid+8 klow,
// a2:row gid khi, a3:row gid+8 khi); u32 holds k pair (even k in low half).
__device__ __forceinline__ int a_frag_u32(int m, int kl) {
    int warpM = m >> 5, mi = (m >> 4) & 1, rb8 = (m >> 3) & 1, gid = m & 7;
    int kk = kl >> 4, k16 = kl & 15;
    int khi = k16 >> 3, t4 = (k16 & 7) >> 1;
    int t4s = (t4 ^ (gid & 3) ^ kk) & 3;
    return ((((kk * 2 + warpM) * 2 + mi) * 8 + gid) * 4 + t4s) * 4 + khi * 2 + rb8;
}

// ---------------- W convert + permute kernel (tiny, one-time) ----------------
__global__ void round_w_kernel(const float* __restrict__ W) {
    int i = blockIdx.x * 256 + threadIdx.x;     // over PREV*DIM
    int k = i / DIM, n = i - k * DIM;
    int kt = k >> 5, kl = k & 31;
    __half h = __float2half_rn(W[i]);
    g_WH[kt * (2 * B_STAGE) + b_frag_half(n, kl)] = __half_as_ushort(h);
}

// ---------------- main fused kernel ----------------
__global__ __launch_bounds__(NTHREADS, 2)
void gemm_tc_scatter_kernel(const float* __restrict__ A,
                            const float* __restrict__ bias,
                            float* __restrict__ out) {
    extern __shared__ uint32_t sm[];
    uint32_t* AsBase = sm;                    // [2][A_STAGE] fragment-major
    uint32_t* BsBase = sm + 2 * A_STAGE;      // [2][B_STAGE] fragment-major

    const int tid = threadIdx.x;
    const int bx  = blockIdx.x;

    // ---- tail blocks: zero padding rows ----
    if (bx >= GRID_GEMM) {
        const int p0 = (bx - GRID_GEMM) * ROWS_PER_Z;
        for (int i = tid; i < ROWS_PER_Z * (DIM / 4); i += NTHREADS) {
            int row = out_row_for_pad(p0 + (i >> 6));
            reinterpret_cast<float4*>(out + (size_t)row * DIM)[i & 63] =
                make_float4(0.f, 0.f, 0.f, 0.f);
        }
        return;
    }

    const int lane   = tid & 31;
    const int warpId = tid >> 5;
    const int warpM  = warpId & 1;      // 0..1 -> 32 rows each
    const int warpN  = warpId >> 1;     // 0..3 -> 64 cols each
    const int nb     = warpN * 64;
    const int gid    = lane >> 2;       // 0..7
    const int t4     = lane & 3;        // 0..3

    const int m0 = bx * BM;

    // A fill coords: thread loads rows am0, am0+32 at ks ak..ak+3 (float4)
    const int am0 = tid >> 3;                 // 0..31
    const int am1 = am0 + 32;
    const int ak  = (tid & 7) * 4;            // 0,4,...,28
    const float* aP0 = A + (size_t)(m0 + am0) * PREV + ak;
    const float* aP1 = A + (size_t)(m0 + am1) * PREV + ak;

    // Per-thread A frag-store u32 slots: pair (ak,ak+1) and (ak+2,ak+3)
    int sa0[2], sa1[2];
    sa0[0] = a_frag_u32(am0, ak);  sa0[1] = a_frag_u32(am0, ak + 2);
    sa1[0] = a_frag_u32(am1, ak);  sa1[1] = a_frag_u32(am1, ak + 2);

    const uint32_t bsm = smem_u32_addr(BsBase);

    float acc[2][8][4];
#pragma unroll
    for (int mi = 0; mi < 2; ++mi)
#pragma unroll
        for (int ni = 0; ni < 8; ++ni)
#pragma unroll
            for (int j = 0; j < 4; ++j) acc[mi][ni][j] = 0.f;

    // ---- prologue: A0 cvt+sts(frag), B0 cp.async; prefetch A1 ----
    {
        float4 a0 = *reinterpret_cast<const float4*>(aP0);
        float4 a1 = *reinterpret_cast<const float4*>(aP1);
        uint32_t* As = AsBase;
        __half2 h;
        h = __float22half2_rn(make_float2(a0.x, a0.y)); As[sa0[0]] = *(uint32_t*)&h;
        h = __float22half2_rn(make_float2(a0.z, a0.w)); As[sa0[1]] = *(uint32_t*)&h;
        h = __float22half2_rn(make_float2(a1.x, a1.y)); As[sa1[0]] = *(uint32_t*)&h;
        h = __float22half2_rn(make_float2(a1.z, a1.w)); As[sa1[1]] = *(uint32_t*)&h;
#pragma unroll
        for (int i = 0; i < 4; ++i) {
            int c = tid + i * NTHREADS;      // 16B chunk index 0..1023
            CP_ASYNC16(bsm + (uint32_t)c * 16, g_WH + c * 8);
        }
        CP_COMMIT();
    }
    float4 pa0 = *reinterpret_cast<const float4*>(aP0 + BK);
    float4 pa1 = *reinterpret_cast<const float4*>(aP1 + BK);

    for (int kt = 0; kt < KTILES; ++kt) {
        const int cur = kt & 1;
        const int nxt = cur ^ 1;
        const bool more = (kt + 1 < KTILES);

        CP_WAIT0();          // B(kt) arrived
        __syncthreads();     // A(kt)+B(kt) visible; stage nxt free

        // kick off B(kt+1) copy (overlaps compute below)
        if (more) {
            const uint16_t* src = g_WH + (size_t)(kt + 1) * (2 * B_STAGE);
#pragma unroll
            for (int i = 0; i < 4; ++i) {
                int c = tid + i * NTHREADS;
                CP_ASYNC16(bsm + (uint32_t)(nxt * B_STAGE + c * 4) * 4, src + c * 8);
            }
            CP_COMMIT();
        }

        // ---- compute current stage: 2 k-steps of 16, fragment-native ----
        const uint32_t* As = AsBase + cur * A_STAGE;
        const uint32_t* Bs = BsBase + cur * B_STAGE;
#pragma unroll
        for (int kk = 0; kk < 2; ++kk) {
            uint32_t af[2][4];
#pragma unroll
            for (int mi = 0; mi < 2; ++mi) {
                int g = ((((kk * 2 + warpM) * 2 + mi) * 8 + gid) * 4 +
                         ((t4 ^ (gid & 3) ^ kk) & 3)) * 4;
                uint4 v = *reinterpret_cast<const uint4*>(As + g);
                af[mi][0] = v.x; af[mi][1] = v.y; af[mi][2] = v.z; af[mi][3] = v.w;
            }
            uint32_t bf[8][2];
#pragma unroll
            for (int ni = 0; ni < 8; ++ni) {
                int g = ((((kk * 4 + warpN) * 8 + ni) * 8 + gid) * 4 + t4) * 2;
                uint2 v = *reinterpret_cast<const uint2*>(Bs + g);
                bf[ni][0] = v.x; bf[ni][1] = v.y;
            }
#pragma unroll
            for (int ni = 0; ni < 8; ++ni) {
                mma_f16(acc[0][ni], af[0], bf[ni]);
                mma_f16(acc[1][ni], af[1], bf[ni]);
            }
        }

        // ---- store A(kt+1) into nxt; prefetch A(kt+2) ----
        if (more) {
            uint32_t* Asn = AsBase + nxt * A_STAGE;
            __half2 h;
            h = __float22half2_rn(make_float2(pa0.x, pa0.y)); Asn[sa0[0]] = *(uint32_t*)&h;
            h = __float22half2_rn(make_float2(pa0.z, pa0.w)); Asn[sa0[1]] = *(uint32_t*)&h;
            h = __float22half2_rn(make_float2(pa1.x, pa1.y)); Asn[sa1[0]] = *(uint32_t*)&h;
            h = __float22half2_rn(make_float2(pa1.z, pa1.w)); Asn[sa1[1]] = *(uint32_t*)&h;
            if (kt + 2 < KTILES) {
                const int k0 = (kt + 2) * BK;
                pa0 = *reinterpret_cast<const float4*>(aP0 + k0);
                pa1 = *reinterpret_cast<const float4*>(aP1 + k0);
            }
        }
    }

    // ---- epilogue: bias + ragged scatter (C layout same as tf32 path) ----
    float2 bv[8];
#pragma unroll
    for (int ni = 0; ni < 8; ++ni)
        bv[ni] = *reinterpret_cast<const float2*>(bias + nb + ni * 8 + 2 * t4);

#pragma unroll
    for (int mi = 0; mi < 2; ++mi) {
        const int r0 = m0 + warpM * 32 + mi * 16 + gid;
        const int o0 = out_row_for_token(r0);
        const int o1 = out_row_for_token(r0 + 8);
        float* p0 = out + (size_t)o0 * DIM + nb + 2 * t4;
        float* p1 = out + (size_t)o1 * DIM + nb + 2 * t4;
#pragma unroll
        for (int ni = 0; ni < 8; ++ni) {
            float2 v0, v1;
            v0.x = acc[mi][ni][0] + bv[ni].x;
            v0.y = acc[mi][ni][1] + bv[ni].y;
            v1.x = acc[mi][ni][2] + bv[ni].x;
            v1.y = acc[mi][ni][3] + bv[ni].y;
            *reinterpret_cast<float2*>(p0 + ni * 8) = v0;
            *reinterpret_cast<float2*>(p1 + ni * 8) = v1;
        }
    }
}

extern "C" void kernel_launch(void* const* d_in, const int* in_sizes, int n_in,
                              void* d_out, int out_size) {
    const float* A    = (const float*)d_in[0];  // sent_embs [T_TOK, PREV]
    const float* W    = (const float*)d_in[1];  // [PREV, DIM]
    const float* bias = (const float*)d_in[2];  // [DIM]
    float* out = (float*)d_out;                 // [NDOCS*MAXLEN, DIM]

    cudaFuncSetAttribute(gemm_tc_scatter_kernel,
                         cudaFuncAttributeMaxDynamicSharedMemorySize, SMEM_BYTES);

    round_w_kernel<<<(PREV * DIM) / 256, 256>>>(W);
    gemm_tc_scatter_kernel<<<GRID_GEMM + ZBLOCKS, NTHREADS, SMEM_BYTES>>>(A, bias, out);
}